// round 2
// baseline (speedup 1.0000x reference)
#include <cuda_runtime.h>
#include <cuda_bf16.h>
#include <cstdint>
#include <cstddef>

// Problem dims (fixed by the dataset)
#define M_TOK 8192   // 4 * 2048 tokens
#define K_DIM 4096
#define N_DIM 4096

// ---------------- scratch (static device globals; no allocation) ----------------
__device__ __align__(16) __nv_bfloat16 g_Aq[(size_t)M_TOK * K_DIM];  // 64 MB quantized activations (integer-valued, bf16)
__device__ __align__(16) __nv_bfloat16 g_Bq[(size_t)N_DIM * K_DIM];  // 32 MB ternary weights (bf16)
__device__ float g_rowscale[M_TOK];   // per-token 1/s = clip(max|x|,1e-5)/127
__device__ float g_partials[4096];    // weight |.| partial sums
__device__ float g_wsc[2];            // [0] = scale_w, [1] = 1/scale_w (= clipped mean|w|)

// ---------------- PTX helpers ----------------
__device__ __forceinline__ uint32_t smem_u32(const void* p) {
    return (uint32_t)__cvta_generic_to_shared(p);
}
__device__ __forceinline__ void cp_async16(void* smem, const void* gmem) {
    asm volatile("cp.async.cg.shared.global [%0], [%1], 16;\n"
                 :: "r"(smem_u32(smem)), "l"(gmem));
}
__device__ __forceinline__ void cp_commit() {
    asm volatile("cp.async.commit_group;\n");
}
template <int N>
__device__ __forceinline__ void cp_wait() {
    asm volatile("cp.async.wait_group %0;\n" :: "n"(N));
}
__device__ __forceinline__ void ldsm4(uint32_t r[4], uint32_t addr) {
    asm volatile("ldmatrix.sync.aligned.m8n8.x4.shared.b16 {%0,%1,%2,%3}, [%4];"
                 : "=r"(r[0]), "=r"(r[1]), "=r"(r[2]), "=r"(r[3]) : "r"(addr));
}
__device__ __forceinline__ void mma16816(float c[4], const uint32_t a[4], uint32_t b0, uint32_t b1) {
    asm volatile("mma.sync.aligned.m16n8k16.row.col.f32.bf16.bf16.f32 "
                 "{%0,%1,%2,%3}, {%4,%5,%6,%7}, {%8,%9}, {%0,%1,%2,%3};"
                 : "+f"(c[0]), "+f"(c[1]), "+f"(c[2]), "+f"(c[3])
                 : "r"(a[0]), "r"(a[1]), "r"(a[2]), "r"(a[3]), "r"(b0), "r"(b1));
}

// ---------------- 1) weight |.| partial reduction (deterministic fixed-order) ----------------
__global__ void wabs_kernel(const float* __restrict__ w) {
    __shared__ float red[256];
    const int b = blockIdx.x, tid = threadIdx.x;
    const float4* wr = (const float4*)(w + (size_t)b * K_DIM);
    float s = 0.f;
#pragma unroll
    for (int i = 0; i < 4; i++) {
        float4 v = wr[tid + i * 256];
        s += fabsf(v.x); s += fabsf(v.y); s += fabsf(v.z); s += fabsf(v.w);
    }
    red[tid] = s; __syncthreads();
    for (int st = 128; st > 0; st >>= 1) {
        if (tid < st) red[tid] += red[tid + st];
        __syncthreads();
    }
    if (tid == 0) g_partials[b] = red[0];
}

__global__ void wfinal_kernel() {
    __shared__ float red[256];
    const int tid = threadIdx.x;
    float s = 0.f;
#pragma unroll
    for (int i = 0; i < 16; i++) s += g_partials[tid + i * 256];
    red[tid] = s; __syncthreads();
    for (int st = 128; st > 0; st >>= 1) {
        if (tid < st) red[tid] += red[tid + st];
        __syncthreads();
    }
    if (tid == 0) {
        float mean = red[0] * (1.0f / (float)((size_t)N_DIM * K_DIM));
        float wm = fmaxf(mean, 1e-5f);     // clip(mean, EPS)
        g_wsc[0] = 1.0f / wm;              // scale_w
        g_wsc[1] = wm;                     // 1/scale_w
    }
}

// ---------------- 2) weight ternarize -> bf16 ----------------
__global__ void quantw_kernel(const float* __restrict__ w) {
    const size_t i = (size_t)blockIdx.x * 256 + threadIdx.x;   // float4 index
    const float sw = g_wsc[0];
    float4 v = ((const float4*)w)[i];
    float a = fminf(fmaxf(rintf(v.x * sw), -1.f), 1.f);
    float b = fminf(fmaxf(rintf(v.y * sw), -1.f), 1.f);
    float c = fminf(fmaxf(rintf(v.z * sw), -1.f), 1.f);
    float d = fminf(fmaxf(rintf(v.w * sw), -1.f), 1.f);
    __nv_bfloat162 p0 = __floats2bfloat162_rn(a, b);
    __nv_bfloat162 p1 = __floats2bfloat162_rn(c, d);
    uint2 o;
    o.x = *(const uint32_t*)&p0;
    o.y = *(const uint32_t*)&p1;
    ((uint2*)g_Bq)[i] = o;
}

// ---------------- 3) per-token activation quant -> bf16 (integer values) ----------------
__global__ void quantx_kernel(const float* __restrict__ x) {
    __shared__ float red[256];
    __shared__ float s_sh;
    const int row = blockIdx.x, tid = threadIdx.x;
    const float4* xr = (const float4*)(x + (size_t)row * K_DIM);
    float4 v[4];
    float mx = 0.f;
#pragma unroll
    for (int i = 0; i < 4; i++) {
        v[i] = xr[tid + i * 256];
        mx = fmaxf(mx, fabsf(v[i].x));
        mx = fmaxf(mx, fabsf(v[i].y));
        mx = fmaxf(mx, fabsf(v[i].z));
        mx = fmaxf(mx, fabsf(v[i].w));
    }
    red[tid] = mx; __syncthreads();
    for (int st = 128; st > 0; st >>= 1) {
        if (tid < st) red[tid] = fmaxf(red[tid], red[tid + st]);
        __syncthreads();
    }
    if (tid == 0) {
        float mc = fmaxf(red[0], 1e-5f);
        float s = 127.0f / mc;
        s_sh = s;
        g_rowscale[row] = 1.0f / s;        // dequant factor, applied in epilogue
    }
    __syncthreads();
    const float s = s_sh;
    uint2* outp = (uint2*)(g_Aq + (size_t)row * K_DIM);
#pragma unroll
    for (int i = 0; i < 4; i++) {
        float a = fminf(fmaxf(rintf(v[i].x * s), -128.f), 127.f);
        float b = fminf(fmaxf(rintf(v[i].y * s), -128.f), 127.f);
        float c = fminf(fmaxf(rintf(v[i].z * s), -128.f), 127.f);
        float d = fminf(fmaxf(rintf(v[i].w * s), -128.f), 127.f);
        __nv_bfloat162 p0 = __floats2bfloat162_rn(a, b);
        __nv_bfloat162 p1 = __floats2bfloat162_rn(c, d);
        uint2 o;
        o.x = *(const uint32_t*)&p0;
        o.y = *(const uint32_t*)&p1;
        outp[tid + i * 256] = o;
    }
}

// ---------------- 4) GEMM: out[m,n] = (Aq[m,:] . Bq[n,:]) * rowscale[m] * (1/scale_w) ----------------
// CTA 128x128x32, 8 warps in 2(m) x 4(n), warp tile 64x32, mma m16n8k16 bf16,
// cp.async 2-stage double buffer, padded smem stride 40 bf16 (80B; conflict-free ldmatrix).
#define BM 128
#define BN 128
#define BK 32
#define LDSM_STRIDE 40

__global__ __launch_bounds__(256) void gemm_kernel(float* __restrict__ out) {
    __shared__ __nv_bfloat16 As[2][BM * LDSM_STRIDE];
    __shared__ __nv_bfloat16 Bs[2][BN * LDSM_STRIDE];

    const int tid  = threadIdx.x;
    const int m0   = blockIdx.y * BM;
    const int n0   = blockIdx.x * BN;
    const int wid  = tid >> 5, lane = tid & 31;
    const int wm   = wid >> 2;        // 0..1
    const int wn   = wid & 3;         // 0..3

    float acc[4][4][4] = {};

    // per-thread staging coordinates: 512 16B-chunks per tile, 2 chunks/thread per operand
    const int trow = tid >> 2;            // 0..63
    const int tcol = (tid & 3) * 8;       // bf16 elems: 0,8,16,24

    const __nv_bfloat16* Ag = g_Aq;
    const __nv_bfloat16* Bg = g_Bq;

    auto issue = [&](int kt, int st) {
        const __nv_bfloat16* ag = Ag + (size_t)(m0 + trow) * K_DIM + kt * BK + tcol;
        const __nv_bfloat16* bg = Bg + (size_t)(n0 + trow) * K_DIM + kt * BK + tcol;
        __nv_bfloat16* as = &As[st][trow * LDSM_STRIDE + tcol];
        __nv_bfloat16* bs = &Bs[st][trow * LDSM_STRIDE + tcol];
        cp_async16(as,                        ag);
        cp_async16(as + 64 * LDSM_STRIDE,     ag + (size_t)64 * K_DIM);
        cp_async16(bs,                        bg);
        cp_async16(bs + 64 * LDSM_STRIDE,     bg + (size_t)64 * K_DIM);
    };

    const int KT = K_DIM / BK;   // 128
    issue(0, 0); cp_commit();

    for (int kt = 0; kt < KT; kt++) {
        const int st = kt & 1;
        if (kt + 1 < KT) { issue(kt + 1, st ^ 1); cp_commit(); cp_wait<1>(); }
        else             { cp_wait<0>(); }
        __syncthreads();

        const __nv_bfloat16* as_base = As[st];
        const __nv_bfloat16* bs_base = Bs[st];
        const int lr = lane & 15;
#pragma unroll
        for (int ks = 0; ks < 2; ks++) {
            const int lc = ks * 16 + (lane >> 4) * 8;
            uint32_t a[4][4], b[2][4];
#pragma unroll
            for (int im = 0; im < 4; im++)
                ldsm4(a[im], smem_u32(&as_base[(wm * 64 + im * 16 + lr) * LDSM_STRIDE + lc]));
#pragma unroll
            for (int ib = 0; ib < 2; ib++)
                ldsm4(b[ib], smem_u32(&bs_base[(wn * 32 + ib * 16 + lr) * LDSM_STRIDE + lc]));
#pragma unroll
            for (int im = 0; im < 4; im++)
#pragma unroll
                for (int jn = 0; jn < 4; jn++)
                    mma16816(acc[im][jn], a[im], b[jn >> 1][jn & 1], b[jn >> 1][2 + (jn & 1)]);
        }
        __syncthreads();
    }

    // epilogue: scale by rowscale[m] * (1/scale_w) and store fp32
    const float wmf = g_wsc[1];
    const int g  = lane >> 2;
    const int tg = lane & 3;
#pragma unroll
    for (int im = 0; im < 4; im++) {
        const int r0 = m0 + wm * 64 + im * 16 + g;
        const float sc0 = g_rowscale[r0] * wmf;
        const float sc1 = g_rowscale[r0 + 8] * wmf;
#pragma unroll
        for (int jn = 0; jn < 4; jn++) {
            const int col = n0 + wn * 32 + jn * 8 + tg * 2;
            float2 v0 = { acc[im][jn][0] * sc0, acc[im][jn][1] * sc0 };
            float2 v1 = { acc[im][jn][2] * sc1, acc[im][jn][3] * sc1 };
            *(float2*)(out + (size_t)r0 * N_DIM + col)       = v0;
            *(float2*)(out + (size_t)(r0 + 8) * N_DIM + col) = v1;
        }
    }
}

// ---------------- launch ----------------
extern "C" void kernel_launch(void* const* d_in, const int* in_sizes, int n_in,
                              void* d_out, int out_size) {
    const float* x = (const float*)d_in[0];
    const float* w = (const float*)d_in[1];
    // defensive: x has 33.5M elems, weight 16.7M
    if (n_in >= 2 && in_sizes[0] == (int)((size_t)N_DIM * K_DIM) &&
        in_sizes[1] == (int)((size_t)M_TOK * K_DIM)) {
        const float* t = x; x = w; w = t;
    }
    float* out = (float*)d_out;

    wabs_kernel<<<4096, 256>>>(w);
    wfinal_kernel<<<1, 256>>>();
    quantw_kernel<<<(N_DIM * (size_t)K_DIM) / 4 / 256, 256>>>(w);
    quantx_kernel<<<M_TOK, 256>>>(x);
    gemm_kernel<<<dim3(N_DIM / BN, M_TOK / BM), 256>>>(out);
}